// round 1
// baseline (speedup 1.0000x reference)
#include <cuda_runtime.h>

#define BATCH 2
#define SEQ   2048
#define HID   1024
#define NHEAD 16
#define HDIM  64
#define MROWS (BATCH*SEQ)   // 4096

// Scratch (allocation-free rule): Q/K/V in [B*NH, S, HD] layout, ctx in [M, H]
__device__ float g_q[MROWS*HID];
__device__ float g_k[MROWS*HID];
__device__ float g_v[MROWS*HID];
__device__ float g_ctx[MROWS*HID];

// ---------------------------------------------------------------------------
// GEMM: C = A[M,K] @ W[N,K]^T + bias[N]
// 64x64 tile, BK=16, 256 threads, 4x4 micro-tile per thread.
// headSplit=1: scatter into [B,NH,S,HD]; headSplit=0: row-major [M,HID].
// ---------------------------------------------------------------------------
__global__ void gemm_bias_kernel(const float* __restrict__ A,
                                 const float* __restrict__ W,
                                 const float* __restrict__ bias,
                                 float* __restrict__ Cout,
                                 int headSplit)
{
    __shared__ float As[16][65];   // [k][m], padded
    __shared__ float Ws[64][17];   // [n][k], padded

    const int tid = threadIdx.x;
    const int tx = tid & 15;
    const int ty = tid >> 4;
    const int m0 = blockIdx.y * 64;
    const int n0 = blockIdx.x * 64;
    const int K  = HID;

    float acc[4][4] = {};

    for (int k0 = 0; k0 < K; k0 += 16) {
        #pragma unroll
        for (int i = 0; i < 4; i++) {
            int idx = tid + i * 256;          // 0..1023
            int r = idx >> 4;                 // tile row 0..63
            int c = idx & 15;                 // k 0..15
            As[c][r] = A[(size_t)(m0 + r) * K + k0 + c];
            Ws[r][c] = W[(size_t)(n0 + r) * K + k0 + c];
        }
        __syncthreads();

        #pragma unroll
        for (int kk = 0; kk < 16; kk++) {
            float a[4], b[4];
            #pragma unroll
            for (int i = 0; i < 4; i++) a[i] = As[kk][ty * 4 + i];
            #pragma unroll
            for (int j = 0; j < 4; j++) b[j] = Ws[tx * 4 + j][kk];
            #pragma unroll
            for (int i = 0; i < 4; i++)
                #pragma unroll
                for (int j = 0; j < 4; j++)
                    acc[i][j] = fmaf(a[i], b[j], acc[i][j]);
        }
        __syncthreads();
    }

    #pragma unroll
    for (int i = 0; i < 4; i++) {
        int m = m0 + ty * 4 + i;
        #pragma unroll
        for (int j = 0; j < 4; j++) {
            int n = n0 + tx * 4 + j;
            float v = acc[i][j] + bias[n];
            if (headSplit) {
                int bb = m >> 11;          // m / SEQ
                int s  = m & (SEQ - 1);
                int h  = n >> 6;           // n / HDIM
                int d  = n & (HDIM - 1);
                Cout[(((size_t)(bb * NHEAD + h)) * SEQ + s) * HDIM + d] = v;
            } else {
                Cout[(size_t)m * HID + n] = v;
            }
        }
    }
}

// ---------------------------------------------------------------------------
// Fused attention: one CTA per (bh, q-tile of 64). Online softmax over k-tiles.
// scores = QK^T * 0.125 + mask[b, k]; ctx written to [M, HID] (heads concat).
// ---------------------------------------------------------------------------
__global__ void attn_kernel(const float* __restrict__ mask,
                            float* __restrict__ ctx)
{
    extern __shared__ float sm[];
    float* Qs    = sm;                 // 64*65
    float* Ks    = Qs + 64 * 65;       // 64*65
    float* Vs    = Ks + 64 * 65;       // 64*65
    float* Ss    = Vs + 64 * 65;       // 64*65
    float* rowm  = Ss + 64 * 65;       // 64
    float* rowl  = rowm + 64;          // 64
    float* rowsc = rowl + 64;          // 64

    const int tid = threadIdx.x;
    const int tx  = tid & 15;
    const int ty  = tid >> 4;
    const int bh  = blockIdx.y;        // 0..31
    const int bb  = bh >> 4;           // batch
    const int h   = bh & 15;           // head
    const int q0  = blockIdx.x * 64;

    const float* Qp = g_q + (size_t)bh * SEQ * HDIM;
    const float* Kp = g_k + (size_t)bh * SEQ * HDIM;
    const float* Vp = g_v + (size_t)bh * SEQ * HDIM;

    #pragma unroll
    for (int i = 0; i < 16; i++) {
        int idx = tid + i * 256;       // 0..4095
        int r = idx >> 6, d = idx & 63;
        Qs[r * 65 + d] = Qp[(size_t)(q0 + r) * HDIM + d];
    }
    if (tid < 64) { rowm[tid] = -1e30f; rowl[tid] = 0.0f; }

    float acc[4][4] = {};
    __syncthreads();

    for (int kt = 0; kt < SEQ / 64; kt++) {
        const int k0 = kt * 64;

        #pragma unroll
        for (int i = 0; i < 16; i++) {
            int idx = tid + i * 256;
            int r = idx >> 6, d = idx & 63;
            Ks[r * 65 + d] = Kp[(size_t)(k0 + r) * HDIM + d];
            Vs[r * 65 + d] = Vp[(size_t)(k0 + r) * HDIM + d];
        }
        __syncthreads();

        // S = Q K^T (4x4 per thread over d=64)
        float s[4][4] = {};
        #pragma unroll
        for (int d = 0; d < 64; d++) {
            float a[4], b[4];
            #pragma unroll
            for (int i = 0; i < 4; i++) a[i] = Qs[(ty * 4 + i) * 65 + d];
            #pragma unroll
            for (int j = 0; j < 4; j++) b[j] = Ks[(tx * 4 + j) * 65 + d];
            #pragma unroll
            for (int i = 0; i < 4; i++)
                #pragma unroll
                for (int j = 0; j < 4; j++)
                    s[i][j] = fmaf(a[i], b[j], s[i][j]);
        }
        #pragma unroll
        for (int j = 0; j < 4; j++) {
            float mk = mask[(size_t)bb * SEQ + k0 + tx * 4 + j];
            #pragma unroll
            for (int i = 0; i < 4; i++)
                Ss[(ty * 4 + i) * 65 + tx * 4 + j] = s[i][j] * 0.125f + mk;
        }
        __syncthreads();

        // online softmax per q-row (64 threads, one row each)
        if (tid < 64) {
            float* row = Ss + tid * 65;
            float tmax = -1e30f;
            #pragma unroll 8
            for (int c = 0; c < 64; c++) tmax = fmaxf(tmax, row[c]);
            float mold = rowm[tid];
            float mnew = fmaxf(mold, tmax);
            float sc   = __expf(mold - mnew);
            float sum  = 0.0f;
            #pragma unroll 8
            for (int c = 0; c < 64; c++) {
                float p = __expf(row[c] - mnew);
                row[c] = p;
                sum += p;
            }
            rowl[tid]  = rowl[tid] * sc + sum;
            rowm[tid]  = mnew;
            rowsc[tid] = sc;
        }
        __syncthreads();

        // rescale accumulator, then acc += P @ V
        float scv[4];
        #pragma unroll
        for (int i = 0; i < 4; i++) scv[i] = rowsc[ty * 4 + i];
        #pragma unroll
        for (int i = 0; i < 4; i++)
            #pragma unroll
            for (int j = 0; j < 4; j++)
                acc[i][j] *= scv[i];

        #pragma unroll
        for (int kk = 0; kk < 64; kk++) {
            float p[4], v[4];
            #pragma unroll
            for (int i = 0; i < 4; i++) p[i] = Ss[(ty * 4 + i) * 65 + kk];
            #pragma unroll
            for (int j = 0; j < 4; j++) v[j] = Vs[kk * 65 + tx * 4 + j];
            #pragma unroll
            for (int i = 0; i < 4; i++)
                #pragma unroll
                for (int j = 0; j < 4; j++)
                    acc[i][j] = fmaf(p[i], v[j], acc[i][j]);
        }
        __syncthreads();
    }

    // ctx[b*SEQ + q, h*64 + d] = acc / l
    #pragma unroll
    for (int i = 0; i < 4; i++) {
        int qr = ty * 4 + i;
        float inv = 1.0f / rowl[qr];
        size_t m = (size_t)bb * SEQ + q0 + qr;
        #pragma unroll
        for (int j = 0; j < 4; j++)
            ctx[m * HID + h * 64 + tx * 4 + j] = acc[i][j] * inv;
    }
}

// ---------------------------------------------------------------------------

extern "C" void kernel_launch(void* const* d_in, const int* in_sizes, int n_in,
                              void* d_out, int out_size)
{
    const float* hs   = (const float*)d_in[0];
    const float* mask = (const float*)d_in[1];
    const float* Wq   = (const float*)d_in[2];
    const float* bq   = (const float*)d_in[3];
    const float* Wk   = (const float*)d_in[4];
    const float* bk   = (const float*)d_in[5];
    const float* Wv   = (const float*)d_in[6];
    const float* bv   = (const float*)d_in[7];
    const float* Wo   = (const float*)d_in[8];
    const float* bo   = (const float*)d_in[9];
    float* out = (float*)d_out;

    float *qptr, *kptr, *vptr, *cptr;
    cudaGetSymbolAddress((void**)&qptr, g_q);
    cudaGetSymbolAddress((void**)&kptr, g_k);
    cudaGetSymbolAddress((void**)&vptr, g_v);
    cudaGetSymbolAddress((void**)&cptr, g_ctx);

    const int attn_smem = (4 * 64 * 65 + 3 * 64) * (int)sizeof(float); // 67,328 B
    cudaFuncSetAttribute(attn_kernel,
                         cudaFuncAttributeMaxDynamicSharedMemorySize, attn_smem);

    dim3 gBlk(256);
    dim3 gGemm(HID / 64, MROWS / 64);   // (16, 64)

    // QKV projections -> head-split layout
    gemm_bias_kernel<<<gGemm, gBlk>>>(hs, Wq, bq, qptr, 1);
    gemm_bias_kernel<<<gGemm, gBlk>>>(hs, Wk, bk, kptr, 1);
    gemm_bias_kernel<<<gGemm, gBlk>>>(hs, Wv, bv, vptr, 1);

    // fused attention
    dim3 gAttn(SEQ / 64, BATCH * NHEAD);  // (32, 32)
    attn_kernel<<<gAttn, gBlk, attn_smem>>>(mask, cptr);

    // output projection -> d_out
    gemm_bias_kernel<<<gGemm, gBlk>>>(cptr, Wo, bo, out, 0);
}

// round 2
// speedup vs baseline: 2.6149x; 2.6149x over previous
#include <cuda_runtime.h>
#include <cuda_bf16.h>

#define BATCH 2
#define SEQ   2048
#define HID   1024
#define NHEAD 16
#define HDIM  64
#define MROWS (BATCH*SEQ)   // 4096

// Scratch (allocation-free rule)
__device__ float g_q[MROWS*HID];
__device__ float g_k[MROWS*HID];
__device__ float g_v[MROWS*HID];
__device__ float g_ctx[MROWS*HID];

// ---------------------------------------------------------------------------
// helpers: bf16x2 packing, fp32 -> (hi,lo) bf16 split, m16n8k16 mma
// ---------------------------------------------------------------------------
__device__ __forceinline__ unsigned pack2(__nv_bfloat16 a, __nv_bfloat16 b) {
    __nv_bfloat162 t(a, b);   // .x = low half = even element
    return *reinterpret_cast<unsigned*>(&t);
}

__device__ __forceinline__ void split2(float x0, float x1,
                                       unsigned &hi, unsigned &lo) {
    __nv_bfloat16 h0 = __float2bfloat16(x0);
    __nv_bfloat16 h1 = __float2bfloat16(x1);
    __nv_bfloat16 l0 = __float2bfloat16(x0 - __bfloat162float(h0));
    __nv_bfloat16 l1 = __float2bfloat16(x1 - __bfloat162float(h1));
    hi = pack2(h0, h1);
    lo = pack2(l0, l1);
}

__device__ __forceinline__ void mma16816(float* c, const unsigned* a,
                                         unsigned b0, unsigned b1) {
    asm volatile(
        "mma.sync.aligned.m16n8k16.row.col.f32.bf16.bf16.f32 "
        "{%0,%1,%2,%3},{%4,%5,%6,%7},{%8,%9},{%0,%1,%2,%3};\n"
        : "+f"(c[0]), "+f"(c[1]), "+f"(c[2]), "+f"(c[3])
        : "r"(a[0]), "r"(a[1]), "r"(a[2]), "r"(a[3]), "r"(b0), "r"(b1));
}

// 3-term emulated-fp32 mma: c += Ahi*Bhi + Alo*Bhi + Ahi*Blo
__device__ __forceinline__ void mma3(float* c,
                                     const unsigned* ah, const unsigned* al,
                                     unsigned bh0, unsigned bh1,
                                     unsigned bl0, unsigned bl1) {
    mma16816(c, ah, bh0, bh1);
    mma16816(c, al, bh0, bh1);
    mma16816(c, ah, bl0, bl1);
}

// ---------------------------------------------------------------------------
// Tensor-core GEMM: C = A[M,K] @ W[N,K]^T + bias[N]
// CTA tile 128(M) x 64(N), k-step 32, 256 threads = 8 warps (4m x 2n),
// warp tile 32x32 (2 m-tiles x 4 n-tiles of m16n8).
// Smem holds bf16x2 pairs: pitch 20 u32 per 16-pair row (conflict-free).
// ---------------------------------------------------------------------------
__global__ __launch_bounds__(256) void gemm_tc_kernel(
    const float* __restrict__ A, const float* __restrict__ W,
    const float* __restrict__ bias, float* __restrict__ Cout, int headSplit)
{
    __shared__ unsigned sAhi[128 * 20];
    __shared__ unsigned sAlo[128 * 20];
    __shared__ unsigned sWhi[64 * 20];
    __shared__ unsigned sWlo[64 * 20];

    const int tid  = threadIdx.x;
    const int lane = tid & 31;
    const int warp = tid >> 5;
    const int wm   = warp >> 1;          // 0..3
    const int wn   = warp & 1;           // 0..1
    const int r    = lane >> 2;          // 0..7
    const int c    = lane & 3;           // 0..3
    const int m0   = blockIdx.y * 128;
    const int n0   = blockIdx.x * 64;

    float acc[2][4][4] = {};

    for (int k0 = 0; k0 < HID; k0 += 32) {
        // load A tile: 128 rows x 16 pairs
        #pragma unroll
        for (int j = 0; j < 8; j++) {
            int idx = tid + j * 256;          // 0..2047
            int row = idx >> 4, p = idx & 15;
            float2 v = *(const float2*)(A + (size_t)(m0 + row) * HID + k0 + p * 2);
            split2(v.x, v.y, sAhi[row * 20 + p], sAlo[row * 20 + p]);
        }
        // load W tile: 64 rows x 16 pairs
        #pragma unroll
        for (int j = 0; j < 4; j++) {
            int idx = tid + j * 256;          // 0..1023
            int row = idx >> 4, p = idx & 15;
            float2 v = *(const float2*)(W + (size_t)(n0 + row) * HID + k0 + p * 2);
            split2(v.x, v.y, sWhi[row * 20 + p], sWlo[row * 20 + p]);
        }
        __syncthreads();

        #pragma unroll
        for (int kk = 0; kk < 2; kk++) {
            unsigned ah[2][4], al[2][4];
            #pragma unroll
            for (int mt = 0; mt < 2; mt++) {
                int base = wm * 32 + mt * 16;
                ah[mt][0] = sAhi[(base + r)     * 20 + kk * 8 + c];
                ah[mt][1] = sAhi[(base + r + 8) * 20 + kk * 8 + c];
                ah[mt][2] = sAhi[(base + r)     * 20 + kk * 8 + c + 4];
                ah[mt][3] = sAhi[(base + r + 8) * 20 + kk * 8 + c + 4];
                al[mt][0] = sAlo[(base + r)     * 20 + kk * 8 + c];
                al[mt][1] = sAlo[(base + r + 8) * 20 + kk * 8 + c];
                al[mt][2] = sAlo[(base + r)     * 20 + kk * 8 + c + 4];
                al[mt][3] = sAlo[(base + r + 8) * 20 + kk * 8 + c + 4];
            }
            #pragma unroll
            for (int nt = 0; nt < 4; nt++) {
                int n = wn * 32 + nt * 8 + r;
                unsigned bh0 = sWhi[n * 20 + kk * 8 + c];
                unsigned bh1 = sWhi[n * 20 + kk * 8 + c + 4];
                unsigned bl0 = sWlo[n * 20 + kk * 8 + c];
                unsigned bl1 = sWlo[n * 20 + kk * 8 + c + 4];
                #pragma unroll
                for (int mt = 0; mt < 2; mt++)
                    mma3(acc[mt][nt], ah[mt], al[mt], bh0, bh1, bl0, bl1);
            }
        }
        __syncthreads();
    }

    // epilogue
    #pragma unroll
    for (int mt = 0; mt < 2; mt++) {
        #pragma unroll
        for (int nt = 0; nt < 4; nt++) {
            int row = m0 + wm * 32 + mt * 16 + r;
            int col = n0 + wn * 32 + nt * 8 + 2 * c;
            float b0 = bias[col], b1 = bias[col + 1];
            float v00 = acc[mt][nt][0] + b0;
            float v01 = acc[mt][nt][1] + b1;
            float v10 = acc[mt][nt][2] + b0;
            float v11 = acc[mt][nt][3] + b1;
            if (headSplit) {
                int h = col >> 6, d = col & 63;
                int bb0 = row >> 11, s0 = row & (SEQ - 1);
                int bb1 = (row + 8) >> 11, s1 = (row + 8) & (SEQ - 1);
                size_t base0 = (((size_t)(bb0 * NHEAD + h)) * SEQ + s0) * HDIM + d;
                size_t base1 = (((size_t)(bb1 * NHEAD + h)) * SEQ + s1) * HDIM + d;
                Cout[base0] = v00; Cout[base0 + 1] = v01;
                Cout[base1] = v10; Cout[base1 + 1] = v11;
            } else {
                Cout[(size_t)row * HID + col]           = v00;
                Cout[(size_t)row * HID + col + 1]       = v01;
                Cout[(size_t)(row + 8) * HID + col]     = v10;
                Cout[(size_t)(row + 8) * HID + col + 1] = v11;
            }
        }
    }
}

// ---------------------------------------------------------------------------
// Tensor-core fused attention. CTA = 128 q-rows of one (b,h); 8 warps x 16 q.
// Online softmax over 32 k-tiles of 64. All matmuls bf16x3 emulated fp32.
// Smem (dynamic): K [kcol][dpair], Vt [d][kpair], P [qrow][kpair] (hi/lo).
// ---------------------------------------------------------------------------
__global__ __launch_bounds__(256) void attn_tc_kernel(
    const float* __restrict__ mask, float* __restrict__ ctx)
{
    extern __shared__ unsigned smU[];
    unsigned* sKhi = smU;                  // 64*36
    unsigned* sKlo = sKhi + 64 * 36;
    unsigned* sVhi = sKlo + 64 * 36;       // [d][kpair]
    unsigned* sVlo = sVhi + 64 * 36;
    unsigned* sPhi = sVlo + 64 * 36;       // 128*36
    unsigned* sPlo = sPhi + 128 * 36;

    const int tid  = threadIdx.x;
    const int lane = tid & 31;
    const int warp = tid >> 5;
    const int r    = lane >> 2;
    const int c    = lane & 3;
    const int bh   = blockIdx.y;           // 0..31
    const int bb   = bh >> 4;
    const int h    = bh & 15;
    const int q0   = blockIdx.x * 128;

    const float* Qp = g_q + (size_t)bh * SEQ * HDIM;
    const float* Kp = g_k + (size_t)bh * SEQ * HDIM;
    const float* Vp = g_v + (size_t)bh * SEQ * HDIM;

    // ---- Q fragments in registers (hi/lo), 16 q-rows per warp ----
    unsigned qh[4][4], ql[4][4];
    {
        int qr  = q0 + warp * 16 + r;
        int qr8 = qr + 8;
        #pragma unroll
        for (int kk = 0; kk < 4; kk++) {
            float2 v0 = *(const float2*)(Qp + (size_t)qr  * HDIM + (kk * 8 + c) * 2);
            float2 v1 = *(const float2*)(Qp + (size_t)qr8 * HDIM + (kk * 8 + c) * 2);
            float2 v2 = *(const float2*)(Qp + (size_t)qr  * HDIM + (kk * 8 + c + 4) * 2);
            float2 v3 = *(const float2*)(Qp + (size_t)qr8 * HDIM + (kk * 8 + c + 4) * 2);
            split2(v0.x, v0.y, qh[kk][0], ql[kk][0]);
            split2(v1.x, v1.y, qh[kk][1], ql[kk][1]);
            split2(v2.x, v2.y, qh[kk][2], ql[kk][2]);
            split2(v3.x, v3.y, qh[kk][3], ql[kk][3]);
        }
    }

    float o[8][4] = {};
    float m_lo = -1e30f, m_hi = -1e30f, l_lo = 0.0f, l_hi = 0.0f;

    for (int kt = 0; kt < SEQ / 64; kt++) {
        const int k0 = kt * 64;

        // ---- load K (row-major pairs) and V (transposed, bf16 halves) ----
        #pragma unroll
        for (int j = 0; j < 8; j++) {
            int idx = tid + j * 256;          // 0..2047
            int row = idx >> 5, p = idx & 31;
            float2 kv = *(const float2*)(Kp + (size_t)(k0 + row) * HDIM + p * 2);
            split2(kv.x, kv.y, sKhi[row * 36 + p], sKlo[row * 36 + p]);

            float2 vv = *(const float2*)(Vp + (size_t)(k0 + row) * HDIM + p * 2);
            // V[row][2p], V[row][2p+1] -> Vt[2p][row], Vt[2p+1][row]
            __nv_bfloat16 h0 = __float2bfloat16(vv.x);
            __nv_bfloat16 h1 = __float2bfloat16(vv.y);
            __nv_bfloat16 l0 = __float2bfloat16(vv.x - __bfloat162float(h0));
            __nv_bfloat16 l1 = __float2bfloat16(vv.y - __bfloat162float(h1));
            int pair = row >> 1, half = row & 1;
            ((__nv_bfloat16*)sVhi)[((2 * p)     * 36 + pair) * 2 + half] = h0;
            ((__nv_bfloat16*)sVhi)[((2 * p + 1) * 36 + pair) * 2 + half] = h1;
            ((__nv_bfloat16*)sVlo)[((2 * p)     * 36 + pair) * 2 + half] = l0;
            ((__nv_bfloat16*)sVlo)[((2 * p + 1) * 36 + pair) * 2 + half] = l1;
        }
        __syncthreads();

        // ---- S = Q K^T (16 x 64 per warp) ----
        float s[8][4] = {};
        #pragma unroll
        for (int kk = 0; kk < 4; kk++) {
            #pragma unroll
            for (int nt = 0; nt < 8; nt++) {
                int n = nt * 8 + r;
                unsigned bh0 = sKhi[n * 36 + kk * 8 + c];
                unsigned bh1 = sKhi[n * 36 + kk * 8 + c + 4];
                unsigned bl0 = sKlo[n * 36 + kk * 8 + c];
                unsigned bl1 = sKlo[n * 36 + kk * 8 + c + 4];
                mma3(s[nt], qh[kk], ql[kk], bh0, bh1, bl0, bl1);
            }
        }

        // ---- scale + mask + online softmax ----
        float tmax_lo = -1e30f, tmax_hi = -1e30f;
        #pragma unroll
        for (int nt = 0; nt < 8; nt++) {
            int col = k0 + nt * 8 + 2 * c;
            float mk0 = mask[(size_t)bb * SEQ + col];
            float mk1 = mask[(size_t)bb * SEQ + col + 1];
            s[nt][0] = s[nt][0] * 0.125f + mk0;
            s[nt][1] = s[nt][1] * 0.125f + mk1;
            s[nt][2] = s[nt][2] * 0.125f + mk0;
            s[nt][3] = s[nt][3] * 0.125f + mk1;
            tmax_lo = fmaxf(tmax_lo, fmaxf(s[nt][0], s[nt][1]));
            tmax_hi = fmaxf(tmax_hi, fmaxf(s[nt][2], s[nt][3]));
        }
        #pragma unroll
        for (int d = 1; d <= 2; d <<= 1) {
            tmax_lo = fmaxf(tmax_lo, __shfl_xor_sync(0xffffffffu, tmax_lo, d));
            tmax_hi = fmaxf(tmax_hi, __shfl_xor_sync(0xffffffffu, tmax_hi, d));
        }
        float mn_lo = fmaxf(m_lo, tmax_lo);
        float mn_hi = fmaxf(m_hi, tmax_hi);
        float scl_lo = __expf(m_lo - mn_lo);
        float scl_hi = __expf(m_hi - mn_hi);
        m_lo = mn_lo; m_hi = mn_hi;

        float sum_lo = 0.0f, sum_hi = 0.0f;
        int prow = warp * 16 + r;
        #pragma unroll
        for (int nt = 0; nt < 8; nt++) {
            float p0 = __expf(s[nt][0] - m_lo);
            float p1 = __expf(s[nt][1] - m_lo);
            float p2 = __expf(s[nt][2] - m_hi);
            float p3 = __expf(s[nt][3] - m_hi);
            sum_lo += p0 + p1;
            sum_hi += p2 + p3;
            split2(p0, p1, sPhi[prow * 36 + nt * 4 + c],
                           sPlo[prow * 36 + nt * 4 + c]);
            split2(p2, p3, sPhi[(prow + 8) * 36 + nt * 4 + c],
                           sPlo[(prow + 8) * 36 + nt * 4 + c]);
        }
        #pragma unroll
        for (int d = 1; d <= 2; d <<= 1) {
            sum_lo += __shfl_xor_sync(0xffffffffu, sum_lo, d);
            sum_hi += __shfl_xor_sync(0xffffffffu, sum_hi, d);
        }
        l_lo = l_lo * scl_lo + sum_lo;
        l_hi = l_hi * scl_hi + sum_hi;

        #pragma unroll
        for (int nt = 0; nt < 8; nt++) {
            o[nt][0] *= scl_lo; o[nt][1] *= scl_lo;
            o[nt][2] *= scl_hi; o[nt][3] *= scl_hi;
        }
        __syncwarp();

        // ---- O += P V (contraction over 64 k-cols) ----
        int pbase = warp * 16;
        #pragma unroll
        for (int kk = 0; kk < 4; kk++) {
            unsigned ah[4], al[4];
            ah[0] = sPhi[(pbase + r)     * 36 + kk * 8 + c];
            ah[1] = sPhi[(pbase + r + 8) * 36 + kk * 8 + c];
            ah[2] = sPhi[(pbase + r)     * 36 + kk * 8 + c + 4];
            ah[3] = sPhi[(pbase + r + 8) * 36 + kk * 8 + c + 4];
            al[0] = sPlo[(pbase + r)     * 36 + kk * 8 + c];
            al[1] = sPlo[(pbase + r + 8) * 36 + kk * 8 + c];
            al[2] = sPlo[(pbase + r)     * 36 + kk * 8 + c + 4];
            al[3] = sPlo[(pbase + r + 8) * 36 + kk * 8 + c + 4];
            #pragma unroll
            for (int nt = 0; nt < 8; nt++) {
                int d = nt * 8 + r;
                unsigned bh0 = sVhi[d * 36 + kk * 8 + c];
                unsigned bh1 = sVhi[d * 36 + kk * 8 + c + 4];
                unsigned bl0 = sVlo[d * 36 + kk * 8 + c];
                unsigned bl1 = sVlo[d * 36 + kk * 8 + c + 4];
                mma3(o[nt], ah, al, bh0, bh1, bl0, bl1);
            }
        }
        __syncthreads();
    }

    // ---- epilogue: ctx[b*SEQ+q][h*64+d] = O / l ----
    float inv_lo = 1.0f / l_lo;
    float inv_hi = 1.0f / l_hi;
    size_t mrow  = (size_t)bb * SEQ + q0 + warp * 16 + r;
    size_t mrow8 = mrow + 8;
    #pragma unroll
    for (int nt = 0; nt < 8; nt++) {
        int col = h * 64 + nt * 8 + 2 * c;
        ctx[mrow  * HID + col]     = o[nt][0] * inv_lo;
        ctx[mrow  * HID + col + 1] = o[nt][1] * inv_lo;
        ctx[mrow8 * HID + col]     = o[nt][2] * inv_hi;
        ctx[mrow8 * HID + col + 1] = o[nt][3] * inv_hi;
    }
}

// ---------------------------------------------------------------------------

extern "C" void kernel_launch(void* const* d_in, const int* in_sizes, int n_in,
                              void* d_out, int out_size)
{
    const float* hs   = (const float*)d_in[0];
    const float* mask = (const float*)d_in[1];
    const float* Wq   = (const float*)d_in[2];
    const float* bq   = (const float*)d_in[3];
    const float* Wk   = (const float*)d_in[4];
    const float* bk   = (const float*)d_in[5];
    const float* Wv   = (const float*)d_in[6];
    const float* bv   = (const float*)d_in[7];
    const float* Wo   = (const float*)d_in[8];
    const float* bo   = (const float*)d_in[9];
    float* out = (float*)d_out;

    float *qptr, *kptr, *vptr, *cptr;
    cudaGetSymbolAddress((void**)&qptr, g_q);
    cudaGetSymbolAddress((void**)&kptr, g_k);
    cudaGetSymbolAddress((void**)&vptr, g_v);
    cudaGetSymbolAddress((void**)&cptr, g_ctx);

    const int attn_smem = (4 * 64 * 36 + 2 * 128 * 36) * (int)sizeof(unsigned); // 73,728 B
    cudaFuncSetAttribute(attn_tc_kernel,
                         cudaFuncAttributeMaxDynamicSharedMemorySize, attn_smem);

    dim3 blk(256);
    dim3 gGemm(HID / 64, MROWS / 128);    // (16, 32)

    gemm_tc_kernel<<<gGemm, blk>>>(hs, Wq, bq, qptr, 1);
    gemm_tc_kernel<<<gGemm, blk>>>(hs, Wk, bk, kptr, 1);
    gemm_tc_kernel<<<gGemm, blk>>>(hs, Wv, bv, vptr, 1);

    dim3 gAttn(SEQ / 128, BATCH * NHEAD); // (16, 32)
    attn_tc_kernel<<<gAttn, blk, attn_smem>>>(mask, cptr);

    gemm_tc_kernel<<<gGemm, blk>>>(cptr, Wo, bo, out, 0);
}

// round 3
// speedup vs baseline: 2.6185x; 1.0014x over previous
#include <cuda_runtime.h>
#include <cuda_bf16.h>

#define BATCH 2
#define SEQ   2048
#define HID   1024
#define NHEAD 16
#define HDIM  64
#define MROWS (BATCH*SEQ)   // 4096

// Scratch (allocation-free rule)
__device__ float g_q[MROWS*HID];
__device__ float g_k[MROWS*HID];
__device__ float g_v[MROWS*HID];
__device__ float g_ctx[MROWS*HID];

// ---------------------------------------------------------------------------
// helpers: bf16x2 packing, fp32 -> (hi,lo) bf16 split, m16n8k16 mma
// ---------------------------------------------------------------------------
__device__ __forceinline__ unsigned pack2(__nv_bfloat16 a, __nv_bfloat16 b) {
    __nv_bfloat162 t(a, b);   // .x = low half = even element
    return *reinterpret_cast<unsigned*>(&t);
}

__device__ __forceinline__ void split2(float x0, float x1,
                                       unsigned &hi, unsigned &lo) {
    __nv_bfloat16 h0 = __float2bfloat16(x0);
    __nv_bfloat16 h1 = __float2bfloat16(x1);
    __nv_bfloat16 l0 = __float2bfloat16(x0 - __bfloat162float(h0));
    __nv_bfloat16 l1 = __float2bfloat16(x1 - __bfloat162float(h1));
    hi = pack2(h0, h1);
    lo = pack2(l0, l1);
}

__device__ __forceinline__ void mma16816(float* c, const unsigned* a,
                                         unsigned b0, unsigned b1) {
    asm volatile(
        "mma.sync.aligned.m16n8k16.row.col.f32.bf16.bf16.f32 "
        "{%0,%1,%2,%3},{%4,%5,%6,%7},{%8,%9},{%0,%1,%2,%3};\n"
        : "+f"(c[0]), "+f"(c[1]), "+f"(c[2]), "+f"(c[3])
        : "r"(a[0]), "r"(a[1]), "r"(a[2]), "r"(a[3]), "r"(b0), "r"(b1));
}

// 3-term emulated-fp32 mma: c += Ahi*Bhi + Alo*Bhi + Ahi*Blo
__device__ __forceinline__ void mma3(float* c,
                                     const unsigned* ah, const unsigned* al,
                                     unsigned bh0, unsigned bh1,
                                     unsigned bl0, unsigned bl1) {
    mma16816(c, ah, bh0, bh1);
    mma16816(c, al, bh0, bh1);
    mma16816(c, ah, bl0, bl1);
}

// ---------------------------------------------------------------------------
// Tensor-core GEMM: C = A[M,K] @ W[N,K]^T + bias[N]
// CTA tile 128(M) x 64(N), k-step 32, 256 threads = 8 warps (4m x 2n),
// warp tile 32x32 (2 m-tiles x 4 n-tiles of m16n8).
// Smem holds bf16x2 pairs: pitch 20 u32 per 16-pair row (conflict-free).
// ---------------------------------------------------------------------------
__global__ __launch_bounds__(256) void gemm_tc_kernel(
    const float* __restrict__ A, const float* __restrict__ W,
    const float* __restrict__ bias, float* __restrict__ Cout, int headSplit)
{
    __shared__ unsigned sAhi[128 * 20];
    __shared__ unsigned sAlo[128 * 20];
    __shared__ unsigned sWhi[64 * 20];
    __shared__ unsigned sWlo[64 * 20];

    const int tid  = threadIdx.x;
    const int lane = tid & 31;
    const int warp = tid >> 5;
    const int wm   = warp >> 1;          // 0..3
    const int wn   = warp & 1;           // 0..1
    const int r    = lane >> 2;          // 0..7
    const int c    = lane & 3;           // 0..3
    const int m0   = blockIdx.y * 128;
    const int n0   = blockIdx.x * 64;

    float acc[2][4][4] = {};

    for (int k0 = 0; k0 < HID; k0 += 32) {
        // load A tile: 128 rows x 16 pairs
        #pragma unroll
        for (int j = 0; j < 8; j++) {
            int idx = tid + j * 256;          // 0..2047
            int row = idx >> 4, p = idx & 15;
            float2 v = *(const float2*)(A + (size_t)(m0 + row) * HID + k0 + p * 2);
            split2(v.x, v.y, sAhi[row * 20 + p], sAlo[row * 20 + p]);
        }
        // load W tile: 64 rows x 16 pairs
        #pragma unroll
        for (int j = 0; j < 4; j++) {
            int idx = tid + j * 256;          // 0..1023
            int row = idx >> 4, p = idx & 15;
            float2 v = *(const float2*)(W + (size_t)(n0 + row) * HID + k0 + p * 2);
            split2(v.x, v.y, sWhi[row * 20 + p], sWlo[row * 20 + p]);
        }
        __syncthreads();

        #pragma unroll
        for (int kk = 0; kk < 2; kk++) {
            unsigned ah[2][4], al[2][4];
            #pragma unroll
            for (int mt = 0; mt < 2; mt++) {
                int base = wm * 32 + mt * 16;
                ah[mt][0] = sAhi[(base + r)     * 20 + kk * 8 + c];
                ah[mt][1] = sAhi[(base + r + 8) * 20 + kk * 8 + c];
                ah[mt][2] = sAhi[(base + r)     * 20 + kk * 8 + c + 4];
                ah[mt][3] = sAhi[(base + r + 8) * 20 + kk * 8 + c + 4];
                al[mt][0] = sAlo[(base + r)     * 20 + kk * 8 + c];
                al[mt][1] = sAlo[(base + r + 8) * 20 + kk * 8 + c];
                al[mt][2] = sAlo[(base + r)     * 20 + kk * 8 + c + 4];
                al[mt][3] = sAlo[(base + r + 8) * 20 + kk * 8 + c + 4];
            }
            #pragma unroll
            for (int nt = 0; nt < 4; nt++) {
                int n = wn * 32 + nt * 8 + r;
                unsigned bh0 = sWhi[n * 20 + kk * 8 + c];
                unsigned bh1 = sWhi[n * 20 + kk * 8 + c + 4];
                unsigned bl0 = sWlo[n * 20 + kk * 8 + c];
                unsigned bl1 = sWlo[n * 20 + kk * 8 + c + 4];
                #pragma unroll
                for (int mt = 0; mt < 2; mt++)
                    mma3(acc[mt][nt], ah[mt], al[mt], bh0, bh1, bl0, bl1);
            }
        }
        __syncthreads();
    }

    // epilogue
    #pragma unroll
    for (int mt = 0; mt < 2; mt++) {
        #pragma unroll
        for (int nt = 0; nt < 4; nt++) {
            int row = m0 + wm * 32 + mt * 16 + r;
            int col = n0 + wn * 32 + nt * 8 + 2 * c;
            float b0 = bias[col], b1 = bias[col + 1];
            float v00 = acc[mt][nt][0] + b0;
            float v01 = acc[mt][nt][1] + b1;
            float v10 = acc[mt][nt][2] + b0;
            float v11 = acc[mt][nt][3] + b1;
            if (headSplit) {
                int h = col >> 6, d = col & 63;
                int bb0 = row >> 11, s0 = row & (SEQ - 1);
                int bb1 = (row + 8) >> 11, s1 = (row + 8) & (SEQ - 1);
                size_t base0 = (((size_t)(bb0 * NHEAD + h)) * SEQ + s0) * HDIM + d;
                size_t base1 = (((size_t)(bb1 * NHEAD + h)) * SEQ + s1) * HDIM + d;
                Cout[base0] = v00; Cout[base0 + 1] = v01;
                Cout[base1] = v10; Cout[base1 + 1] = v11;
            } else {
                Cout[(size_t)row * HID + col]           = v00;
                Cout[(size_t)row * HID + col + 1]       = v01;
                Cout[(size_t)(row + 8) * HID + col]     = v10;
                Cout[(size_t)(row + 8) * HID + col + 1] = v11;
            }
        }
    }
}

// ---------------------------------------------------------------------------
// Tensor-core fused attention. CTA = 128 q-rows of one (b,h); 8 warps x 16 q.
// Online softmax over 32 k-tiles of 64. All matmuls bf16x3 emulated fp32.
// Smem (dynamic): K [kcol][dpair], Vt [d][kpair], P [qrow][kpair] (hi/lo).
// ---------------------------------------------------------------------------
__global__ __launch_bounds__(256) void attn_tc_kernel(
    const float* __restrict__ mask, float* __restrict__ ctx)
{
    extern __shared__ unsigned smU[];
    unsigned* sKhi = smU;                  // 64*36
    unsigned* sKlo = sKhi + 64 * 36;
    unsigned* sVhi = sKlo + 64 * 36;       // [d][kpair]
    unsigned* sVlo = sVhi + 64 * 36;
    unsigned* sPhi = sVlo + 64 * 36;       // 128*36
    unsigned* sPlo = sPhi + 128 * 36;

    const int tid  = threadIdx.x;
    const int lane = tid & 31;
    const int warp = tid >> 5;
    const int r    = lane >> 2;
    const int c    = lane & 3;
    const int bh   = blockIdx.y;           // 0..31
    const int bb   = bh >> 4;
    const int h    = bh & 15;
    const int q0   = blockIdx.x * 128;

    const float* Qp = g_q + (size_t)bh * SEQ * HDIM;
    const float* Kp = g_k + (size_t)bh * SEQ * HDIM;
    const float* Vp = g_v + (size_t)bh * SEQ * HDIM;

    // ---- Q fragments in registers (hi/lo), 16 q-rows per warp ----
    unsigned qh[4][4], ql[4][4];
    {
        int qr  = q0 + warp * 16 + r;
        int qr8 = qr + 8;
        #pragma unroll
        for (int kk = 0; kk < 4; kk++) {
            float2 v0 = *(const float2*)(Qp + (size_t)qr  * HDIM + (kk * 8 + c) * 2);
            float2 v1 = *(const float2*)(Qp + (size_t)qr8 * HDIM + (kk * 8 + c) * 2);
            float2 v2 = *(const float2*)(Qp + (size_t)qr  * HDIM + (kk * 8 + c + 4) * 2);
            float2 v3 = *(const float2*)(Qp + (size_t)qr8 * HDIM + (kk * 8 + c + 4) * 2);
            split2(v0.x, v0.y, qh[kk][0], ql[kk][0]);
            split2(v1.x, v1.y, qh[kk][1], ql[kk][1]);
            split2(v2.x, v2.y, qh[kk][2], ql[kk][2]);
            split2(v3.x, v3.y, qh[kk][3], ql[kk][3]);
        }
    }

    float o[8][4] = {};
    float m_lo = -1e30f, m_hi = -1e30f, l_lo = 0.0f, l_hi = 0.0f;

    for (int kt = 0; kt < SEQ / 64; kt++) {
        const int k0 = kt * 64;

        // ---- load K (row-major pairs) and V (transposed, bf16 halves) ----
        #pragma unroll
        for (int j = 0; j < 8; j++) {
            int idx = tid + j * 256;          // 0..2047
            int row = idx >> 5, p = idx & 31;
            float2 kv = *(const float2*)(Kp + (size_t)(k0 + row) * HDIM + p * 2);
            split2(kv.x, kv.y, sKhi[row * 36 + p], sKlo[row * 36 + p]);

            float2 vv = *(const float2*)(Vp + (size_t)(k0 + row) * HDIM + p * 2);
            // V[row][2p], V[row][2p+1] -> Vt[2p][row], Vt[2p+1][row]
            __nv_bfloat16 h0 = __float2bfloat16(vv.x);
            __nv_bfloat16 h1 = __float2bfloat16(vv.y);
            __nv_bfloat16 l0 = __float2bfloat16(vv.x - __bfloat162float(h0));
            __nv_bfloat16 l1 = __float2bfloat16(vv.y - __bfloat162float(h1));
            int pair = row >> 1, half = row & 1;
            ((__nv_bfloat16*)sVhi)[((2 * p)     * 36 + pair) * 2 + half] = h0;
            ((__nv_bfloat16*)sVhi)[((2 * p + 1) * 36 + pair) * 2 + half] = h1;
            ((__nv_bfloat16*)sVlo)[((2 * p)     * 36 + pair) * 2 + half] = l0;
            ((__nv_bfloat16*)sVlo)[((2 * p + 1) * 36 + pair) * 2 + half] = l1;
        }
        __syncthreads();

        // ---- S = Q K^T (16 x 64 per warp) ----
        float s[8][4] = {};
        #pragma unroll
        for (int kk = 0; kk < 4; kk++) {
            #pragma unroll
            for (int nt = 0; nt < 8; nt++) {
                int n = nt * 8 + r;
                unsigned bh0 = sKhi[n * 36 + kk * 8 + c];
                unsigned bh1 = sKhi[n * 36 + kk * 8 + c + 4];
                unsigned bl0 = sKlo[n * 36 + kk * 8 + c];
                unsigned bl1 = sKlo[n * 36 + kk * 8 + c + 4];
                mma3(s[nt], qh[kk], ql[kk], bh0, bh1, bl0, bl1);
            }
        }

        // ---- scale + mask + online softmax ----
        float tmax_lo = -1e30f, tmax_hi = -1e30f;
        #pragma unroll
        for (int nt = 0; nt < 8; nt++) {
            int col = k0 + nt * 8 + 2 * c;
            float mk0 = mask[(size_t)bb * SEQ + col];
            float mk1 = mask[(size_t)bb * SEQ + col + 1];
            s[nt][0] = s[nt][0] * 0.125f + mk0;
            s[nt][1] = s[nt][1] * 0.125f + mk1;
            s[nt][2] = s[nt][2] * 0.125f + mk0;
            s[nt][3] = s[nt][3] * 0.125f + mk1;
            tmax_lo = fmaxf(tmax_lo, fmaxf(s[nt][0], s[nt][1]));
            tmax_hi = fmaxf(tmax_hi, fmaxf(s[nt][2], s[nt][3]));
        }
        #pragma unroll
        for (int d = 1; d <= 2; d <<= 1) {
            tmax_lo = fmaxf(tmax_lo, __shfl_xor_sync(0xffffffffu, tmax_lo, d));
            tmax_hi = fmaxf(tmax_hi, __shfl_xor_sync(0xffffffffu, tmax_hi, d));
        }
        float mn_lo = fmaxf(m_lo, tmax_lo);
        float mn_hi = fmaxf(m_hi, tmax_hi);
        float scl_lo = __expf(m_lo - mn_lo);
        float scl_hi = __expf(m_hi - mn_hi);
        m_lo = mn_lo; m_hi = mn_hi;

        float sum_lo = 0.0f, sum_hi = 0.0f;
        int prow = warp * 16 + r;
        #pragma unroll
        for (int nt = 0; nt < 8; nt++) {
            float p0 = __expf(s[nt][0] - m_lo);
            float p1 = __expf(s[nt][1] - m_lo);
            float p2 = __expf(s[nt][2] - m_hi);
            float p3 = __expf(s[nt][3] - m_hi);
            sum_lo += p0 + p1;
            sum_hi += p2 + p3;
            split2(p0, p1, sPhi[prow * 36 + nt * 4 + c],
                           sPlo[prow * 36 + nt * 4 + c]);
            split2(p2, p3, sPhi[(prow + 8) * 36 + nt * 4 + c],
                           sPlo[(prow + 8) * 36 + nt * 4 + c]);
        }
        #pragma unroll
        for (int d = 1; d <= 2; d <<= 1) {
            sum_lo += __shfl_xor_sync(0xffffffffu, sum_lo, d);
            sum_hi += __shfl_xor_sync(0xffffffffu, sum_hi, d);
        }
        l_lo = l_lo * scl_lo + sum_lo;
        l_hi = l_hi * scl_hi + sum_hi;

        #pragma unroll
        for (int nt = 0; nt < 8; nt++) {
            o[nt][0] *= scl_lo; o[nt][1] *= scl_lo;
            o[nt][2] *= scl_hi; o[nt][3] *= scl_hi;
        }
        __syncwarp();

        // ---- O += P V (contraction over 64 k-cols) ----
        int pbase = warp * 16;
        #pragma unroll
        for (int kk = 0; kk < 4; kk++) {
            unsigned ah[4], al[4];
            ah[0] = sPhi[(pbase + r)     * 36 + kk * 8 + c];
            ah[1] = sPhi[(pbase + r + 8) * 36 + kk * 8 + c];
            ah[2] = sPhi[(pbase + r)     * 36 + kk * 8 + c + 4];
            ah[3] = sPhi[(pbase + r + 8) * 36 + kk * 8 + c + 4];
            al[0] = sPlo[(pbase + r)     * 36 + kk * 8 + c];
            al[1] = sPlo[(pbase + r + 8) * 36 + kk * 8 + c];
            al[2] = sPlo[(pbase + r)     * 36 + kk * 8 + c + 4];
            al[3] = sPlo[(pbase + r + 8) * 36 + kk * 8 + c + 4];
            #pragma unroll
            for (int nt = 0; nt < 8; nt++) {
                int d = nt * 8 + r;
                unsigned bh0 = sVhi[d * 36 + kk * 8 + c];
                unsigned bh1 = sVhi[d * 36 + kk * 8 + c + 4];
                unsigned bl0 = sVlo[d * 36 + kk * 8 + c];
                unsigned bl1 = sVlo[d * 36 + kk * 8 + c + 4];
                mma3(o[nt], ah, al, bh0, bh1, bl0, bl1);
            }
        }
        __syncthreads();
    }

    // ---- epilogue: ctx[b*SEQ+q][h*64+d] = O / l ----
    float inv_lo = 1.0f / l_lo;
    float inv_hi = 1.0f / l_hi;
    size_t mrow  = (size_t)bb * SEQ + q0 + warp * 16 + r;
    size_t mrow8 = mrow + 8;
    #pragma unroll
    for (int nt = 0; nt < 8; nt++) {
        int col = h * 64 + nt * 8 + 2 * c;
        ctx[mrow  * HID + col]     = o[nt][0] * inv_lo;
        ctx[mrow  * HID + col + 1] = o[nt][1] * inv_lo;
        ctx[mrow8 * HID + col]     = o[nt][2] * inv_hi;
        ctx[mrow8 * HID + col + 1] = o[nt][3] * inv_hi;
    }
}

// ---------------------------------------------------------------------------

extern "C" void kernel_launch(void* const* d_in, const int* in_sizes, int n_in,
                              void* d_out, int out_size)
{
    const float* hs   = (const float*)d_in[0];
    const float* mask = (const float*)d_in[1];
    const float* Wq   = (const float*)d_in[2];
    const float* bq   = (const float*)d_in[3];
    const float* Wk   = (const float*)d_in[4];
    const float* bk   = (const float*)d_in[5];
    const float* Wv   = (const float*)d_in[6];
    const float* bv   = (const float*)d_in[7];
    const float* Wo   = (const float*)d_in[8];
    const float* bo   = (const float*)d_in[9];
    float* out = (float*)d_out;

    float *qptr, *kptr, *vptr, *cptr;
    cudaGetSymbolAddress((void**)&qptr, g_q);
    cudaGetSymbolAddress((void**)&kptr, g_k);
    cudaGetSymbolAddress((void**)&vptr, g_v);
    cudaGetSymbolAddress((void**)&cptr, g_ctx);

    const int attn_smem = (4 * 64 * 36 + 2 * 128 * 36) * (int)sizeof(unsigned); // 73,728 B
    cudaFuncSetAttribute(attn_tc_kernel,
                         cudaFuncAttributeMaxDynamicSharedMemorySize, attn_smem);

    dim3 blk(256);
    dim3 gGemm(HID / 64, MROWS / 128);    // (16, 32)

    gemm_tc_kernel<<<gGemm, blk>>>(hs, Wq, bq, qptr, 1);
    gemm_tc_kernel<<<gGemm, blk>>>(hs, Wk, bk, kptr, 1);
    gemm_tc_kernel<<<gGemm, blk>>>(hs, Wv, bv, vptr, 1);

    dim3 gAttn(SEQ / 128, BATCH * NHEAD); // (16, 32)
    attn_tc_kernel<<<gAttn, blk, attn_smem>>>(mask, cptr);

    gemm_tc_kernel<<<gGemm, blk>>>(cptr, Wo, bo, out, 0);
}